// round 1
// baseline (speedup 1.0000x reference)
#include <cuda_runtime.h>

#define B_  4
#define T_  2048
#define C_  1024
#define NH_ 16
#define HS_ 64
#define M_  (B_*T_)      // 8192

// Scratch (allocation-free rule: __device__ globals)
__device__ float g_q[B_*NH_*T_*HS_];   // [B,NH,T,HS]
__device__ float g_k[B_*NH_*T_*HS_];
__device__ float g_v[B_*NH_*T_*HS_];
__device__ float g_y[B_*T_*C_];        // [B,T,C]

// ---------------------------------------------------------------------------
// GEMM: Out[m,n] = sum_k A[m,k]*W[n,k] + bias[n]   (both operands K-major)
// 128x128 tile, BK=16, 256 threads, 8x8 per thread.
// MODE 1: A = x param, epilogue scatters into g_q/g_k/g_v ([B,NH,T,HS])
// MODE 2: A = g_y,     epilogue writes Out (d_out) with bias
// ---------------------------------------------------------------------------
template <int MODE>
__global__ __launch_bounds__(256)
void gemm_nt(const float* __restrict__ A, const float* __restrict__ W,
             const float* __restrict__ bias, float* __restrict__ Out,
             int Ndim, int Kdim)
{
    __shared__ float As[16][128];
    __shared__ float Bs[16][128];

    const int tid = threadIdx.x;
    const int bm = blockIdx.y, bn = blockIdx.x;
    const int tx = tid & 15, ty = tid >> 4;
    const int lrow = tid >> 1;
    const int lk = (tid & 1) << 3;

    const float* Asrc = (MODE == 2) ? (const float*)g_y : A;
    const float* aptr = Asrc + (size_t)(bm * 128 + lrow) * Kdim + lk;
    const float* bptr = W    + (size_t)(bn * 128 + lrow) * Kdim + lk;

    float acc[8][8];
#pragma unroll
    for (int i = 0; i < 8; i++)
#pragma unroll
        for (int j = 0; j < 8; j++) acc[i][j] = 0.f;

    for (int kt = 0; kt < Kdim; kt += 16) {
        float4 a0 = *(const float4*)(aptr + kt);
        float4 a1 = *(const float4*)(aptr + kt + 4);
        float4 b0 = *(const float4*)(bptr + kt);
        float4 b1 = *(const float4*)(bptr + kt + 4);
        __syncthreads();
        As[lk+0][lrow]=a0.x; As[lk+1][lrow]=a0.y; As[lk+2][lrow]=a0.z; As[lk+3][lrow]=a0.w;
        As[lk+4][lrow]=a1.x; As[lk+5][lrow]=a1.y; As[lk+6][lrow]=a1.z; As[lk+7][lrow]=a1.w;
        Bs[lk+0][lrow]=b0.x; Bs[lk+1][lrow]=b0.y; Bs[lk+2][lrow]=b0.z; Bs[lk+3][lrow]=b0.w;
        Bs[lk+4][lrow]=b1.x; Bs[lk+5][lrow]=b1.y; Bs[lk+6][lrow]=b1.z; Bs[lk+7][lrow]=b1.w;
        __syncthreads();
#pragma unroll
        for (int kk = 0; kk < 16; kk++) {
            float af[8], bf[8];
            *(float4*)&af[0] = *(const float4*)&As[kk][ty*8];
            *(float4*)&af[4] = *(const float4*)&As[kk][ty*8+4];
            *(float4*)&bf[0] = *(const float4*)&Bs[kk][tx*8];
            *(float4*)&bf[4] = *(const float4*)&Bs[kk][tx*8+4];
#pragma unroll
            for (int i = 0; i < 8; i++)
#pragma unroll
                for (int j = 0; j < 8; j++)
                    acc[i][j] += af[i] * bf[j];
        }
    }

    const int n0 = bn * 128 + tx * 8;
    float bia[8];
#pragma unroll
    for (int j = 0; j < 8; j++) bia[j] = bias[n0 + j];

    if (MODE == 1) {
        // n0 is a multiple of 8 -> 8-wide chunk stays inside one head & one of q/k/v
        const int sel = n0 >> 10;
        const int nn  = n0 & 1023;
        const int h   = nn >> 6;
        const int hs0 = nn & 63;
        float* dst = (sel == 0) ? g_q : ((sel == 1) ? g_k : g_v);
#pragma unroll
        for (int i = 0; i < 8; i++) {
            const int m  = bm * 128 + ty * 8 + i;
            const int bb = m >> 11;        // / T_
            const int t  = m & 2047;
            float* p = dst + (((size_t)(bb * NH_ + h) * T_ + t) << 6) + hs0;
            *(float4*)(p)   = make_float4(acc[i][0]+bia[0], acc[i][1]+bia[1],
                                          acc[i][2]+bia[2], acc[i][3]+bia[3]);
            *(float4*)(p+4) = make_float4(acc[i][4]+bia[4], acc[i][5]+bia[5],
                                          acc[i][6]+bia[6], acc[i][7]+bia[7]);
        }
    } else {
#pragma unroll
        for (int i = 0; i < 8; i++) {
            const int m = bm * 128 + ty * 8 + i;
            float* p = Out + (size_t)m * Ndim + n0;
            *(float4*)(p)   = make_float4(acc[i][0]+bia[0], acc[i][1]+bia[1],
                                          acc[i][2]+bia[2], acc[i][3]+bia[3]);
            *(float4*)(p+4) = make_float4(acc[i][4]+bia[4], acc[i][5]+bia[5],
                                          acc[i][6]+bia[6], acc[i][7]+bia[7]);
        }
    }
}

// ---------------------------------------------------------------------------
// Flash attention, fp32, causal. BM=BN=64, 256 threads (16x16), 4x4 tiles with
// strided mapping (rows ty+16i, cols tx+16j) so shfl row-reductions live in a
// 16-lane half-warp. Q/K/P smem XOR-swizzled (col ^ (row&31)) for conflict-free
// scalar access. P aliases the K buffer => static smem = 3*16KB = 48KB exactly.
// ---------------------------------------------------------------------------
__global__ __launch_bounds__(256)
void attn_kernel()
{
    __shared__ float Qs [64*64];
    __shared__ float KPs[64*64];
    __shared__ float Vs [64*64];

    const int qt = gridDim.x - 1 - blockIdx.x;  // heavy tiles first
    const int h  = blockIdx.y;
    const int b  = blockIdx.z;
    const int tid = threadIdx.x;
    const int tx = tid & 15, ty = tid >> 4;

    const size_t bh = (size_t)(b * NH_ + h) * (T_ * HS_);
    const float* Qg = g_q + bh + (size_t)qt * (64 * HS_);

    // Load Q, pre-scaled by 1/sqrt(HS)=0.125, swizzled
#pragma unroll
    for (int it = 0; it < 4; it++) {
        int idx = (it * 256 + tid) * 4;
        int r = idx >> 6, c = idx & 63;
        float4 qv = *(const float4*)(Qg + idx);
        int rb = r & 31;
        Qs[r*64 + ((c+0)^rb)] = qv.x * 0.125f;
        Qs[r*64 + ((c+1)^rb)] = qv.y * 0.125f;
        Qs[r*64 + ((c+2)^rb)] = qv.z * 0.125f;
        Qs[r*64 + ((c+3)^rb)] = qv.w * 0.125f;
    }

    float m_i[4], l_i[4], o[4][4];
#pragma unroll
    for (int i = 0; i < 4; i++) {
        m_i[i] = -1e30f; l_i[i] = 0.f;
#pragma unroll
        for (int j = 0; j < 4; j++) o[i][j] = 0.f;
    }

    for (int kt = 0; kt <= qt; kt++) {
        const float* Kg = g_k + bh + (size_t)kt * (64 * HS_);
        const float* Vg = g_v + bh + (size_t)kt * (64 * HS_);
        float4 kreg[4], vreg[4];
#pragma unroll
        for (int it = 0; it < 4; it++) {
            int idx = (it * 256 + tid) * 4;
            kreg[it] = *(const float4*)(Kg + idx);
            vreg[it] = *(const float4*)(Vg + idx);
        }
        __syncthreads();   // prev PV reads of KPs/Vs complete (also covers Q store, iter 0)
#pragma unroll
        for (int it = 0; it < 4; it++) {
            int idx = (it * 256 + tid) * 4;
            int r = idx >> 6, c = idx & 63;
            int rb = r & 31;
            KPs[r*64 + ((c+0)^rb)] = kreg[it].x;
            KPs[r*64 + ((c+1)^rb)] = kreg[it].y;
            KPs[r*64 + ((c+2)^rb)] = kreg[it].z;
            KPs[r*64 + ((c+3)^rb)] = kreg[it].w;
            *(float4*)&Vs[r*64 + c] = vreg[it];
        }
        __syncthreads();

        // S = Q K^T (pre-scaled)
        float s[4][4];
#pragma unroll
        for (int i = 0; i < 4; i++)
#pragma unroll
            for (int j = 0; j < 4; j++) s[i][j] = 0.f;

#pragma unroll 8
        for (int d = 0; d < 64; d++) {
            float qv[4], kv[4];
#pragma unroll
            for (int i = 0; i < 4; i++) {
                int r = ty + 16*i;
                qv[i] = Qs[r*64 + (d ^ (r & 31))];
            }
#pragma unroll
            for (int j = 0; j < 4; j++) {
                int r = tx + 16*j;
                kv[j] = KPs[r*64 + (d ^ (r & 31))];
            }
#pragma unroll
            for (int i = 0; i < 4; i++)
#pragma unroll
                for (int j = 0; j < 4; j++)
                    s[i][j] += qv[i] * kv[j];
        }

        if (kt == qt) {   // diagonal tile: causal mask
#pragma unroll
            for (int i = 0; i < 4; i++) {
                int r = ty + 16*i;
#pragma unroll
                for (int j = 0; j < 4; j++)
                    if (tx + 16*j > r) s[i][j] = -1e30f;
            }
        }

        __syncthreads();   // all K reads done before P overwrites KPs

        // online softmax + write P
#pragma unroll
        for (int i = 0; i < 4; i++) {
            float mt = fmaxf(fmaxf(s[i][0], s[i][1]), fmaxf(s[i][2], s[i][3]));
            mt = fmaxf(mt, __shfl_xor_sync(0xffffffffu, mt, 8));
            mt = fmaxf(mt, __shfl_xor_sync(0xffffffffu, mt, 4));
            mt = fmaxf(mt, __shfl_xor_sync(0xffffffffu, mt, 2));
            mt = fmaxf(mt, __shfl_xor_sync(0xffffffffu, mt, 1));
            float mnew = fmaxf(m_i[i], mt);
            float corr = __expf(m_i[i] - mnew);
            m_i[i] = mnew;
            float rs = 0.f;
#pragma unroll
            for (int j = 0; j < 4; j++) {
                s[i][j] = __expf(s[i][j] - mnew);
                rs += s[i][j];
            }
            rs += __shfl_xor_sync(0xffffffffu, rs, 8);
            rs += __shfl_xor_sync(0xffffffffu, rs, 4);
            rs += __shfl_xor_sync(0xffffffffu, rs, 2);
            rs += __shfl_xor_sync(0xffffffffu, rs, 1);
            l_i[i] = l_i[i] * corr + rs;
#pragma unroll
            for (int j = 0; j < 4; j++) o[i][j] *= corr;
            int r = ty + 16*i, rb = r & 31;
#pragma unroll
            for (int j = 0; j < 4; j++)
                KPs[r*64 + ((tx + 16*j) ^ rb)] = s[i][j];
        }
        __syncthreads();

        // O += P V
#pragma unroll 8
        for (int n = 0; n < 64; n++) {
            float pv[4], vv[4];
#pragma unroll
            for (int i = 0; i < 4; i++) {
                int r = ty + 16*i;
                pv[i] = KPs[r*64 + (n ^ (r & 31))];
            }
#pragma unroll
            for (int j = 0; j < 4; j++)
                vv[j] = Vs[n*64 + tx + 16*j];
#pragma unroll
            for (int i = 0; i < 4; i++)
#pragma unroll
                for (int j = 0; j < 4; j++)
                    o[i][j] += pv[i] * vv[j];
        }
        // top-of-loop sync protects next overwrite
    }

    // normalize + write y [B,T,C]
#pragma unroll
    for (int i = 0; i < 4; i++) {
        float inv = 1.f / l_i[i];
        int row = qt * 64 + ty + 16*i;
        float* yp = g_y + ((size_t)b * T_ + row) * C_ + h * HS_;
#pragma unroll
        for (int j = 0; j < 4; j++)
            yp[tx + 16*j] = o[i][j] * inv;
    }
}

// ---------------------------------------------------------------------------
extern "C" void kernel_launch(void* const* d_in, const int* in_sizes, int n_in,
                              void* d_out, int out_size)
{
    (void)in_sizes; (void)n_in; (void)out_size;
    const float* x     = (const float*)d_in[0];
    const float* Wqkv  = (const float*)d_in[1];
    const float* bqkv  = (const float*)d_in[2];
    const float* Wproj = (const float*)d_in[3];
    const float* bproj = (const float*)d_in[4];
    float* out = (float*)d_out;

    // 1) QKV projection -> g_q/g_k/g_v
    dim3 g1(3 * C_ / 128, M_ / 128);   // (24, 64)
    gemm_nt<1><<<g1, 256>>>(x, Wqkv, bqkv, nullptr, 3 * C_, C_);

    // 2) causal flash attention -> g_y
    dim3 g2(T_ / 64, NH_, B_);         // (32, 16, 4)
    attn_kernel<<<g2, 256>>>();

    // 3) output projection -> d_out
    dim3 g3(C_ / 128, M_ / 128);       // (8, 64)
    gemm_nt<2><<<g3, 256>>>(nullptr, Wproj, bproj, out, C_, C_);
}

// round 3
// speedup vs baseline: 1.2187x; 1.2187x over previous
#include <cuda_runtime.h>
#include <cuda_bf16.h>
#include <cstdint>

#define B_  4
#define T_  2048
#define C_  1024
#define NH_ 16
#define HS_ 64
#define M_  (B_*T_)      // 8192

// ---------------- scratch (__device__ globals; no allocation allowed) -------
__device__ float g_q[B_*NH_*T_*HS_];   // [B,NH,T,HS] fp32
__device__ float g_k[B_*NH_*T_*HS_];
__device__ float g_v[B_*NH_*T_*HS_];
__device__ float g_y[B_*T_*C_];        // [B,T,C]   fp32

// bf16 split buffers (a = hi + lo)
__device__ __nv_bfloat16 g_ah[M_*C_];       // activation hi (x, then y reused)
__device__ __nv_bfloat16 g_al[M_*C_];       // activation lo
__device__ __nv_bfloat16 g_wqh[3*C_*C_];    // Wqkv hi
__device__ __nv_bfloat16 g_wql[3*C_*C_];
__device__ __nv_bfloat16 g_wph[C_*C_];      // Wproj hi
__device__ __nv_bfloat16 g_wpl[C_*C_];

// ---------------- helpers ---------------------------------------------------
__device__ __forceinline__ uint32_t smem_u32(const void* p) {
    uint32_t a;
    asm("{ .reg .u64 t; cvta.to.shared.u64 t, %1; cvt.u32.u64 %0, t; }" : "=r"(a) : "l"(p));
    return a;
}

#define LDMX4(r0, r1, r2, r3, addr)                                              \
    asm volatile("ldmatrix.sync.aligned.m8n8.x4.shared.b16 {%0,%1,%2,%3}, [%4];" \
        : "=r"(r0), "=r"(r1), "=r"(r2), "=r"(r3) : "r"(addr))

#define MMA16816(d, a0, a1, a2, a3, b0, b1)                                      \
    asm volatile("mma.sync.aligned.m16n8k16.row.col.f32.bf16.bf16.f32 "          \
        "{%0,%1,%2,%3}, {%4,%5,%6,%7}, {%8,%9}, {%0,%1,%2,%3};"                  \
        : "+f"((d)[0]), "+f"((d)[1]), "+f"((d)[2]), "+f"((d)[3])                 \
        : "r"(a0), "r"(a1), "r"(a2), "r"(a3), "r"(b0), "r"(b1))

// ---------------- split fp32 -> bf16 hi/lo ----------------------------------
__global__ __launch_bounds__(256)
void split_kernel(const float* __restrict__ src, __nv_bfloat16* __restrict__ hi,
                  __nv_bfloat16* __restrict__ lo, int n4)
{
    int i = blockIdx.x * 256 + threadIdx.x;
    if (i >= n4) return;
    float4 v = ((const float4*)src)[i];
    __nv_bfloat16 h0 = __float2bfloat16_rn(v.x);
    __nv_bfloat16 h1 = __float2bfloat16_rn(v.y);
    __nv_bfloat16 h2 = __float2bfloat16_rn(v.z);
    __nv_bfloat16 h3 = __float2bfloat16_rn(v.w);
    __nv_bfloat162 hh0; hh0.x = h0; hh0.y = h1;
    __nv_bfloat162 hh1; hh1.x = h2; hh1.y = h3;
    __nv_bfloat162 ll0, ll1;
    ll0.x = __float2bfloat16_rn(v.x - __bfloat162float(h0));
    ll0.y = __float2bfloat16_rn(v.y - __bfloat162float(h1));
    ll1.x = __float2bfloat16_rn(v.z - __bfloat162float(h2));
    ll1.y = __float2bfloat16_rn(v.w - __bfloat162float(h3));
    ((__nv_bfloat162*)hi)[i*2]   = hh0;
    ((__nv_bfloat162*)hi)[i*2+1] = hh1;
    ((__nv_bfloat162*)lo)[i*2]   = ll0;
    ((__nv_bfloat162*)lo)[i*2+1] = ll1;
}

// ---------------- HMMA GEMM --------------------------------------------------
#define PADK 40   // bf16 per smem row (32 data + 8 pad) = 80 bytes

struct GemmSmem {
    __nv_bfloat16 A[2][128][PADK];
    __nv_bfloat16 B[2][128][PADK];
};

template <int MODE>  // 1: scatter into g_q/g_k/g_v ; 2: Out + bias
__global__ __launch_bounds__(256)
void gemm_hmma(const __nv_bfloat16* __restrict__ Ah, const __nv_bfloat16* __restrict__ Al,
               const __nv_bfloat16* __restrict__ Wh, const __nv_bfloat16* __restrict__ Wl,
               const float* __restrict__ bias, float* __restrict__ Out)
{
    __shared__ GemmSmem sm;
    const int tid  = threadIdx.x;
    const int bm   = blockIdx.y, bn = blockIdx.x;
    const int warp = tid >> 5, lane = tid & 31;
    const int warpM = warp & 3, warpN = warp >> 2;

    const uint32_t sA = smem_u32(&sm.A[0][0][0]);
    const uint32_t sB = smem_u32(&sm.B[0][0][0]);
    const uint32_t BUF = 128 * PADK * 2;  // bytes per buffer

    const int lrow = tid >> 1;
    const int lcol = (tid & 1) * 16;
    const size_t arowoff = (size_t)(bm * 128 + lrow) * C_ + lcol;
    const size_t browoff = (size_t)(bn * 128 + lrow) * C_ + lcol;

    const int rowA_l = warpM * 32 + (lane & 15);
    const int colA_l = (lane >> 4) * 8;
    const int rowB_l = warpN * 64 + (lane & 7) + (lane >> 4) * 8;
    const int colB_l = ((lane >> 3) & 1) * 8;

    float acc[2][8][4];
#pragma unroll
    for (int mf = 0; mf < 2; mf++)
#pragma unroll
        for (int nf = 0; nf < 8; nf++)
#pragma unroll
            for (int r = 0; r < 4; r++) acc[mf][nf][r] = 0.f;

    const int NIT = 96;  // 3 passes * (1024/32)
    uint4 rA0, rA1, rB0, rB1;

    rA0 = *(const uint4*)(Ah + arowoff);
    rA1 = *(const uint4*)(Ah + arowoff + 8);
    rB0 = *(const uint4*)(Wh + browoff);
    rB1 = *(const uint4*)(Wh + browoff + 8);
    *(uint4*)(sm.A[0][lrow] + lcol)     = rA0;
    *(uint4*)(sm.A[0][lrow] + lcol + 8) = rA1;
    *(uint4*)(sm.B[0][lrow] + lcol)     = rB0;
    *(uint4*)(sm.B[0][lrow] + lcol + 8) = rB1;

    int cur = 0;
    for (int it = 0; it < NIT; it++) {
        __syncthreads();
        if (it + 1 < NIT) {
            const int nit = it + 1;
            const int pass = nit >> 5;
            const int kb = (nit & 31) * 32;
            const __nv_bfloat16* Ap = (pass < 2) ? Ah : Al;
            const __nv_bfloat16* Wp = (pass == 1) ? Wl : Wh;
            rA0 = *(const uint4*)(Ap + arowoff + kb);
            rA1 = *(const uint4*)(Ap + arowoff + kb + 8);
            rB0 = *(const uint4*)(Wp + browoff + kb);
            rB1 = *(const uint4*)(Wp + browoff + kb + 8);
        }
        const uint32_t aBase = sA + (uint32_t)cur * BUF;
        const uint32_t bBase = sB + (uint32_t)cur * BUF;
#pragma unroll
        for (int k16 = 0; k16 < 2; k16++) {
            uint32_t a0[4], a1[4];
            LDMX4(a0[0], a0[1], a0[2], a0[3],
                  aBase + (uint32_t)((rowA_l)      * PADK + colA_l + k16 * 16) * 2);
            LDMX4(a1[0], a1[1], a1[2], a1[3],
                  aBase + (uint32_t)((rowA_l + 16) * PADK + colA_l + k16 * 16) * 2);
#pragma unroll
            for (int ng = 0; ng < 4; ng++) {
                uint32_t b[4];
                LDMX4(b[0], b[1], b[2], b[3],
                      bBase + (uint32_t)((rowB_l + ng * 16) * PADK + colB_l + k16 * 16) * 2);
                MMA16816(acc[0][ng*2],   a0[0], a0[1], a0[2], a0[3], b[0], b[1]);
                MMA16816(acc[0][ng*2+1], a0[0], a0[1], a0[2], a0[3], b[2], b[3]);
                MMA16816(acc[1][ng*2],   a1[0], a1[1], a1[2], a1[3], b[0], b[1]);
                MMA16816(acc[1][ng*2+1], a1[0], a1[1], a1[2], a1[3], b[2], b[3]);
            }
        }
        if (it + 1 < NIT) {
            const int nxt = cur ^ 1;
            *(uint4*)(sm.A[nxt][lrow] + lcol)     = rA0;
            *(uint4*)(sm.A[nxt][lrow] + lcol + 8) = rA1;
            *(uint4*)(sm.B[nxt][lrow] + lcol)     = rB0;
            *(uint4*)(sm.B[nxt][lrow] + lcol + 8) = rB1;
        }
        cur ^= 1;
    }

    // ---------------- epilogue ----------------
    const int mrow0 = bm * 128 + warpM * 32;
    const int ncol0 = bn * 128 + warpN * 64;
    const int lq = lane >> 2, lr = lane & 3;
#pragma unroll
    for (int mf = 0; mf < 2; mf++) {
#pragma unroll
        for (int nf = 0; nf < 8; nf++) {
            const int n = ncol0 + nf * 8 + lr * 2;
            const float b0 = bias[n], b1 = bias[n + 1];
#pragma unroll
            for (int half = 0; half < 2; half++) {
                const int m = mrow0 + mf * 16 + lq + half * 8;
                float2 v;
                v.x = acc[mf][nf][half * 2 + 0] + b0;
                v.y = acc[mf][nf][half * 2 + 1] + b1;
                if (MODE == 1) {
                    const int sel = n >> 10;
                    float* dstb = (sel == 0) ? g_q : (sel == 1) ? g_k : g_v;
                    const int h   = (n & 1023) >> 6;
                    const int hs0 = n & 63;
                    const int bb = m >> 11, t = m & 2047;
                    *(float2*)(dstb + (((size_t)(bb * NH_ + h) * T_ + t) << 6) + hs0) = v;
                } else {
                    *(float2*)(Out + (size_t)m * C_ + n) = v;
                }
            }
        }
    }
}

// ---------------------------------------------------------------------------
// Flash attention, fp32, causal (unchanged — known good).
// ---------------------------------------------------------------------------
__global__ __launch_bounds__(256)
void attn_kernel()
{
    __shared__ float Qs [64*64];
    __shared__ float KPs[64*64];
    __shared__ float Vs [64*64];

    const int qt = gridDim.x - 1 - blockIdx.x;
    const int h  = blockIdx.y;
    const int b  = blockIdx.z;
    const int tid = threadIdx.x;
    const int tx = tid & 15, ty = tid >> 4;

    const size_t bh = (size_t)(b * NH_ + h) * (T_ * HS_);
    const float* Qg = g_q + bh + (size_t)qt * (64 * HS_);

#pragma unroll
    for (int it = 0; it < 4; it++) {
        int idx = (it * 256 + tid) * 4;
        int r = idx >> 6, c = idx & 63;
        float4 qv = *(const float4*)(Qg + idx);
        int rb = r & 31;
        Qs[r*64 + ((c+0)^rb)] = qv.x * 0.125f;
        Qs[r*64 + ((c+1)^rb)] = qv.y * 0.125f;
        Qs[r*64 + ((c+2)^rb)] = qv.z * 0.125f;
        Qs[r*64 + ((c+3)^rb)] = qv.w * 0.125f;
    }

    float m_i[4], l_i[4], o[4][4];
#pragma unroll
    for (int i = 0; i < 4; i++) {
        m_i[i] = -1e30f; l_i[i] = 0.f;
#pragma unroll
        for (int j = 0; j < 4; j++) o[i][j] = 0.f;
    }

    for (int kt = 0; kt <= qt; kt++) {
        const float* Kg = g_k + bh + (size_t)kt * (64 * HS_);
        const float* Vg = g_v + bh + (size_t)kt * (64 * HS_);
        float4 kreg[4], vreg[4];
#pragma unroll
        for (int it = 0; it < 4; it++) {
            int idx = (it * 256 + tid) * 4;
            kreg[it] = *(const float4*)(Kg + idx);
            vreg[it] = *(const float4*)(Vg + idx);
        }
        __syncthreads();
#pragma unroll
        for (int it = 0; it < 4; it++) {
            int idx = (it * 256 + tid) * 4;
            int r = idx >> 6, c = idx & 63;
            int rb = r & 31;
            KPs[r*64 + ((c+0)^rb)] = kreg[it].x;
            KPs[r*64 + ((c+1)^rb)] = kreg[it].y;
            KPs[r*64 + ((c+2)^rb)] = kreg[it].z;
            KPs[r*64 + ((c+3)^rb)] = kreg[it].w;
            *(float4*)&Vs[r*64 + c] = vreg[it];
        }
        __syncthreads();

        float s[4][4];
#pragma unroll
        for (int i = 0; i < 4; i++)
#pragma unroll
            for (int j = 0; j < 4; j++) s[i][j] = 0.f;

#pragma unroll 8
        for (int d = 0; d < 64; d++) {
            float qv[4], kv[4];
#pragma unroll
            for (int i = 0; i < 4; i++) {
                int r = ty + 16*i;
                qv[i] = Qs[r*64 + (d ^ (r & 31))];
            }
#pragma unroll
            for (int j = 0; j < 4; j++) {
                int r = tx + 16*j;
                kv[j] = KPs[r*64 + (d ^ (r & 31))];
            }
#pragma unroll
            for (int i = 0; i < 4; i++)
#pragma unroll
                for (int j = 0; j < 4; j++)
                    s[i][j] += qv[i] * kv[j];
        }

        if (kt == qt) {
#pragma unroll
            for (int i = 0; i < 4; i++) {
                int r = ty + 16*i;
#pragma unroll
                for (int j = 0; j < 4; j++)
                    if (tx + 16*j > r) s[i][j] = -1e30f;
            }
        }

        __syncthreads();

#pragma unroll
        for (int i = 0; i < 4; i++) {
            float mt = fmaxf(fmaxf(s[i][0], s[i][1]), fmaxf(s[i][2], s[i][3]));
            mt = fmaxf(mt, __shfl_xor_sync(0xffffffffu, mt, 8));
            mt = fmaxf(mt, __shfl_xor_sync(0xffffffffu, mt, 4));
            mt = fmaxf(mt, __shfl_xor_sync(0xffffffffu, mt, 2));
            mt = fmaxf(mt, __shfl_xor_sync(0xffffffffu, mt, 1));
            float mnew = fmaxf(m_i[i], mt);
            float corr = __expf(m_i[i] - mnew);
            m_i[i] = mnew;
            float rs = 0.f;
#pragma unroll
            for (int j = 0; j < 4; j++) {
                s[i][j] = __expf(s[i][j] - mnew);
                rs += s[i][j];
            }
            rs += __shfl_xor_sync(0xffffffffu, rs, 8);
            rs += __shfl_xor_sync(0xffffffffu, rs, 4);
            rs += __shfl_xor_sync(0xffffffffu, rs, 2);
            rs += __shfl_xor_sync(0xffffffffu, rs, 1);
            l_i[i] = l_i[i] * corr + rs;
#pragma unroll
            for (int j = 0; j < 4; j++) o[i][j] *= corr;
            int r = ty + 16*i, rb = r & 31;
#pragma unroll
            for (int j = 0; j < 4; j++)
                KPs[r*64 + ((tx + 16*j) ^ rb)] = s[i][j];
        }
        __syncthreads();

#pragma unroll 8
        for (int n = 0; n < 64; n++) {
            float pv[4], vv[4];
#pragma unroll
            for (int i = 0; i < 4; i++) {
                int r = ty + 16*i;
                pv[i] = KPs[r*64 + (n ^ (r & 31))];
            }
#pragma unroll
            for (int j = 0; j < 4; j++)
                vv[j] = Vs[n*64 + tx + 16*j];
#pragma unroll
            for (int i = 0; i < 4; i++)
#pragma unroll
                for (int j = 0; j < 4; j++)
                    o[i][j] += pv[i] * vv[j];
        }
    }

#pragma unroll
    for (int i = 0; i < 4; i++) {
        float inv = 1.f / l_i[i];
        int row = qt * 64 + ty + 16*i;
        float* yp = g_y + ((size_t)b * T_ + row) * C_ + h * HS_;
#pragma unroll
        for (int j = 0; j < 4; j++)
            yp[tx + 16*j] = o[i][j] * inv;
    }
}

// ---------------------------------------------------------------------------
extern "C" void kernel_launch(void* const* d_in, const int* in_sizes, int n_in,
                              void* d_out, int out_size)
{
    (void)in_sizes; (void)n_in; (void)out_size;
    const float* x     = (const float*)d_in[0];
    const float* Wqkv  = (const float*)d_in[1];
    const float* bqkv  = (const float*)d_in[2];
    const float* Wproj = (const float*)d_in[3];
    const float* bproj = (const float*)d_in[4];
    float* out = (float*)d_out;

    __nv_bfloat16 *ah, *al, *wqh, *wql, *wph, *wpl;
    cudaGetSymbolAddress((void**)&ah,  g_ah);
    cudaGetSymbolAddress((void**)&al,  g_al);
    cudaGetSymbolAddress((void**)&wqh, g_wqh);
    cudaGetSymbolAddress((void**)&wql, g_wql);
    cudaGetSymbolAddress((void**)&wph, g_wph);
    cudaGetSymbolAddress((void**)&wpl, g_wpl);
    float* yptr;
    cudaGetSymbolAddress((void**)&yptr, g_y);

    split_kernel<<<(M_*C_/4 + 255)/256, 256>>>(x, ah, al, M_*C_/4);
    split_kernel<<<(3*C_*C_/4 + 255)/256, 256>>>(Wqkv, wqh, wql, 3*C_*C_/4);
    split_kernel<<<(C_*C_/4 + 255)/256, 256>>>(Wproj, wph, wpl, C_*C_/4);

    gemm_hmma<1><<<dim3(3*C_/128, M_/128), 256>>>(ah, al, wqh, wql, bqkv, nullptr);

    attn_kernel<<<dim3(T_/64, NH_, B_), 256>>>();

    split_kernel<<<(M_*C_/4 + 255)/256, 256>>>(yptr, ah, al, M_*C_/4);
    gemm_hmma<2><<<dim3(C_/128, M_/128), 256>>>(ah, al, wph, wpl, bproj, out);
}

// round 8
// speedup vs baseline: 2.8051x; 2.3017x over previous
#include <cuda_runtime.h>
#include <cuda_bf16.h>
#include <cstdint>

#define B_  4
#define T_  2048
#define C_  1024
#define NH_ 16
#define HS_ 64
#define M_  (B_*T_)      // 8192

#define QSCALE 0.18033688011112042f   // 0.125 * log2(e)

// ---------------- scratch (__device__ globals; no allocation) ---------------
__device__ __nv_bfloat16 g_qh[B_*NH_*T_*HS_];   // [B,NH,T,HS] bf16 splits
__device__ __nv_bfloat16 g_ql[B_*NH_*T_*HS_];
__device__ __nv_bfloat16 g_kh[B_*NH_*T_*HS_];
__device__ __nv_bfloat16 g_kl[B_*NH_*T_*HS_];
__device__ __nv_bfloat16 g_vh[B_*NH_*T_*HS_];
__device__ __nv_bfloat16 g_vl[B_*NH_*T_*HS_];
__device__ __nv_bfloat16 g_ah[M_*C_];           // activation hi (x, then y)
__device__ __nv_bfloat16 g_al[M_*C_];
__device__ __nv_bfloat16 g_wqh[3*C_*C_];
__device__ __nv_bfloat16 g_wql[3*C_*C_];
__device__ __nv_bfloat16 g_wph[C_*C_];
__device__ __nv_bfloat16 g_wpl[C_*C_];

// ---------------- helpers ---------------------------------------------------
__device__ __forceinline__ uint32_t smem_u32(const void* p) {
    uint32_t a;
    asm("{ .reg .u64 t; cvta.to.shared.u64 t, %1; cvt.u32.u64 %0, t; }" : "=r"(a) : "l"(p));
    return a;
}
#define LDMX4(r0, r1, r2, r3, addr)                                              \
    asm volatile("ldmatrix.sync.aligned.m8n8.x4.shared.b16 {%0,%1,%2,%3}, [%4];" \
        : "=r"(r0), "=r"(r1), "=r"(r2), "=r"(r3) : "r"(addr))
#define LDMX4T(r0, r1, r2, r3, addr)                                             \
    asm volatile("ldmatrix.sync.aligned.m8n8.x4.trans.shared.b16 {%0,%1,%2,%3}, [%4];" \
        : "=r"(r0), "=r"(r1), "=r"(r2), "=r"(r3) : "r"(addr))
#define MMA16816(d, a0, a1, a2, a3, b0, b1)                                      \
    asm volatile("mma.sync.aligned.m16n8k16.row.col.f32.bf16.bf16.f32 "          \
        "{%0,%1,%2,%3}, {%4,%5,%6,%7}, {%8,%9}, {%0,%1,%2,%3};"                  \
        : "+f"((d)[0]), "+f"((d)[1]), "+f"((d)[2]), "+f"((d)[3])                 \
        : "r"(a0), "r"(a1), "r"(a2), "r"(a3), "r"(b0), "r"(b1))
#define CP16(dst, src)                                                            \
    asm volatile("cp.async.cg.shared.global [%0], [%1], 16;" :: "r"(dst), "l"(src))
#define CPCOMMIT() asm volatile("cp.async.commit_group;")
#define CPWAIT1()  asm volatile("cp.async.wait_group 1;")
#define CPWAIT0()  asm volatile("cp.async.wait_group 0;")

__device__ __forceinline__ float ex2f(float x) {
    float r;
    asm("ex2.approx.ftz.f32 %0, %1;" : "=f"(r) : "f"(x));
    return r;
}
__device__ __forceinline__ float rcpf(float x) {
    float r;
    asm("rcp.approx.ftz.f32 %0, %1;" : "=f"(r) : "f"(x));
    return r;
}
__device__ __forceinline__ uint32_t packbf(float x, float y) {
    __nv_bfloat162 t;
    t.x = __float2bfloat16_rn(x); t.y = __float2bfloat16_rn(y);
    return *(uint32_t*)&t;
}
__device__ __forceinline__ void split2(float x, float y, uint32_t& hi, uint32_t& lo) {
    __nv_bfloat16 hx = __float2bfloat16_rn(x), hy = __float2bfloat16_rn(y);
    __nv_bfloat162 h; h.x = hx; h.y = hy;
    __nv_bfloat162 l;
    l.x = __float2bfloat16_rn(x - __bfloat162float(hx));
    l.y = __float2bfloat16_rn(y - __bfloat162float(hy));
    hi = *(uint32_t*)&h; lo = *(uint32_t*)&l;
}

// ---------------- split fp32 -> bf16 hi/lo ----------------------------------
__global__ __launch_bounds__(256)
void split_kernel(const float* __restrict__ src, __nv_bfloat16* __restrict__ hi,
                  __nv_bfloat16* __restrict__ lo, int n4)
{
    int i = blockIdx.x * 256 + threadIdx.x;
    if (i >= n4) return;
    float4 v = ((const float4*)src)[i];
    uint32_t h0, l0, h1, l1;
    split2(v.x, v.y, h0, l0);
    split2(v.z, v.w, h1, l1);
    ((uint32_t*)hi)[i*2]   = h0;
    ((uint32_t*)hi)[i*2+1] = h1;
    ((uint32_t*)lo)[i*2]   = l0;
    ((uint32_t*)lo)[i*2+1] = l1;
}

// ---------------- HMMA GEMM (cp.async 3-stage) -------------------------------
// Out[m,n] = sum_k A[m,k]*W[n,k] + bias[n]; bf16x3 (Ah*Wh + Ah*Wl + Al*Wh).
// CTA 128x128, BK=32, 8 warps (4x2), warp 32x64.
// MODE 1: epilogue splits to g_q*/g_k*/g_v* bf16 hi/lo (q scaled by QSCALE).
// MODE 2: Out = fp32 + bias.
#define PADK 40                       // bf16 per smem row (80 B)
#define GSTAGE_B (128*PADK*2)         // bytes per matrix per stage (10240)
#define GSMEM_BYTES (3 * 2 * GSTAGE_B)

template <int MODE>
__global__ __launch_bounds__(256, 2)
void gemm_hmma(const __nv_bfloat16* __restrict__ Ah, const __nv_bfloat16* __restrict__ Al,
               const __nv_bfloat16* __restrict__ Wh, const __nv_bfloat16* __restrict__ Wl,
               const float* __restrict__ bias, float* __restrict__ Out)
{
    extern __shared__ __nv_bfloat16 gsm[];
    const uint32_t sbase = smem_u32(gsm);
    const int tid  = threadIdx.x;
    const int bm   = blockIdx.y, bn = blockIdx.x;
    const int warp = tid >> 5, lane = tid & 31;
    const int warpM = warp & 3, warpN = warp >> 2;

    const int lrow = tid >> 1;
    const int lcol = (tid & 1) * 16;
    const size_t arowoff = (size_t)(bm * 128 + lrow) * C_ + lcol;
    const size_t browoff = (size_t)(bn * 128 + lrow) * C_ + lcol;
    const uint32_t dstoff = (uint32_t)(lrow * PADK + lcol) * 2;

    const int rowA_l = warpM * 32 + (lane & 15);
    const int colA_l = (lane >> 4) * 8;
    const int rowB_l = warpN * 64 + (lane & 7) + (lane >> 4) * 8;
    const int colB_l = ((lane >> 3) & 1) * 8;

    float acc[2][8][4];
#pragma unroll
    for (int mf = 0; mf < 2; mf++)
#pragma unroll
        for (int nf = 0; nf < 8; nf++)
#pragma unroll
            for (int r = 0; r < 4; r++) acc[mf][nf][r] = 0.f;

    const int NIT = 96;  // 3 passes * 32

    // issue loads for iteration 'it' into stage s
    auto issue = [&](int s, int it) {
        const int pass = it >> 5;
        const int kb = (it & 31) * 32;
        const __nv_bfloat16* Ap = (pass < 2) ? Ah : Al;
        const __nv_bfloat16* Wp = (pass == 1) ? Wl : Wh;
        const uint32_t aDst = sbase + (uint32_t)s * (2 * GSTAGE_B) + dstoff;
        const uint32_t bDst = aDst + GSTAGE_B;
        CP16(aDst,      Ap + arowoff + kb);
        CP16(aDst + 16, Ap + arowoff + kb + 8);
        CP16(bDst,      Wp + browoff + kb);
        CP16(bDst + 16, Wp + browoff + kb + 8);
    };

    issue(0, 0); CPCOMMIT();
    issue(1, 1); CPCOMMIT();

    for (int it = 0; it < NIT; it++) {
        CPWAIT1();          // stage it%3 complete (pending = {it, it+1})
        __syncthreads();
        if (it + 2 < NIT) issue((it + 2) % 3, it + 2);
        CPCOMMIT();
        const uint32_t aBase = sbase + (uint32_t)(it % 3) * (2 * GSTAGE_B);
        const uint32_t bBase = aBase + GSTAGE_B;
#pragma unroll
        for (int k16 = 0; k16 < 2; k16++) {
            uint32_t a0[4], a1[4];
            LDMX4(a0[0], a0[1], a0[2], a0[3],
                  aBase + (uint32_t)((rowA_l)      * PADK + colA_l + k16 * 16) * 2);
            LDMX4(a1[0], a1[1], a1[2], a1[3],
                  aBase + (uint32_t)((rowA_l + 16) * PADK + colA_l + k16 * 16) * 2);
#pragma unroll
            for (int ng = 0; ng < 4; ng++) {
                uint32_t b[4];
                LDMX4(b[0], b[1], b[2], b[3],
                      bBase + (uint32_t)((rowB_l + ng * 16) * PADK + colB_l + k16 * 16) * 2);
                MMA16816(acc[0][ng*2],   a0[0], a0[1], a0[2], a0[3], b[0], b[1]);
                MMA16816(acc[0][ng*2+1], a0[0], a0[1], a0[2], a0[3], b[2], b[3]);
                MMA16816(acc[1][ng*2],   a1[0], a1[1], a1[2], a1[3], b[0], b[1]);
                MMA16816(acc[1][ng*2+1], a1[0], a1[1], a1[2], a1[3], b[2], b[3]);
            }
        }
    }

    // ---------------- epilogue ----------------
    const int mrow0 = bm * 128 + warpM * 32;
    const int ncol0 = bn * 128 + warpN * 64;
    const int lq = lane >> 2, lr = lane & 3;
#pragma unroll
    for (int mf = 0; mf < 2; mf++) {
#pragma unroll
        for (int nf = 0; nf < 8; nf++) {
            const int n = ncol0 + nf * 8 + lr * 2;
            const float b0 = bias[n], b1 = bias[n + 1];
#pragma unroll
            for (int half = 0; half < 2; half++) {
                const int m = mrow0 + mf * 16 + lq + half * 8;
                float v0 = acc[mf][nf][half * 2 + 0] + b0;
                float v1 = acc[mf][nf][half * 2 + 1] + b1;
                if (MODE == 1) {
                    const int sel = n >> 10;
                    if (sel == 0) { v0 *= QSCALE; v1 *= QSCALE; }
                    __nv_bfloat16* dh = (sel == 0) ? g_qh : (sel == 1) ? g_kh : g_vh;
                    __nv_bfloat16* dl = (sel == 0) ? g_ql : (sel == 1) ? g_kl : g_vl;
                    const int h   = (n & 1023) >> 6;
                    const int hs0 = n & 63;
                    const int bb = m >> 11, t = m & 2047;
                    const size_t idx = (((size_t)(bb * NH_ + h) * T_ + t) << 6) + hs0;
                    uint32_t hi, lo;
                    split2(v0, v1, hi, lo);
                    *(uint32_t*)(dh + idx) = hi;
                    *(uint32_t*)(dl + idx) = lo;
                } else {
                    float2 v; v.x = v0; v.y = v1;
                    *(float2*)(Out + (size_t)m * C_ + n) = v;
                }
            }
        }
    }
}

// ---------------- HMMA flash attention ---------------------------------------
// BM=128 (8 warps x m16), BN=64. bf16x3 for QK and PV. Base-2 softmax
// (Q pre-scaled by 0.125*log2e). Double-buffered KV via cp.async.
// Writes y directly as bf16 hi/lo into g_ah/g_al ([B,T,C]).
#define AP 72                         // padded row stride (bf16)
#define SQH 0
#define SQL (128*AP)                  // 9216
#define SKV0 (2*128*AP)               // 18432
#define KVSTAGE (4*64*AP)             // 18432 elems per stage (Kh,Kl,Vh,Vl)
#define ATTN_SMEM_BYTES ((SKV0 + 2*KVSTAGE) * 2)   // 110592 B

__global__ __launch_bounds__(256, 2)
void attn_hmma()
{
    extern __shared__ __nv_bfloat16 asm_[];
    const uint32_t sbase = smem_u32(asm_);
    const int tid  = threadIdx.x;
    const int warp = tid >> 5, lane = tid & 31;
    const int lq = lane >> 2, lr = lane & 3;

    const int qt = (int)gridDim.x - 1 - (int)blockIdx.x;  // heavy first
    const int h  = blockIdx.y;
    const int b  = blockIdx.z;
    const size_t bh = (size_t)(b * NH_ + h) * (T_ * HS_);

    // ---- load Q (hi+lo) into smem ----
#pragma unroll
    for (int i = 0; i < 4; i++) {
        int c = i * 256 + tid;               // 1024 chunks of 8 bf16
        int row = c >> 3, col = (c & 7) * 8;
        const size_t src = bh + (size_t)(qt * 128 + row) * 64 + col;
        *(uint4*)(asm_ + SQH + row * AP + col) = *(const uint4*)(g_qh + src);
        *(uint4*)(asm_ + SQL + row * AP + col) = *(const uint4*)(g_ql + src);
    }

    // cp.async issue for KV tile kv into stage s
    auto issue_kv = [&](int s, int kv) {
        const uint32_t stg = sbase + (uint32_t)(SKV0 + s * KVSTAGE) * 2;
#pragma unroll
        for (int i = 0; i < 2; i++) {
            int c = i * 256 + tid;           // 512 chunks per array
            int row = c >> 3, col = (c & 7) * 8;
            const size_t src = bh + (size_t)(kv * 64 + row) * 64 + col;
            const uint32_t d = stg + (uint32_t)(row * AP + col) * 2;
            CP16(d,                      g_kh + src);
            CP16(d + (64*AP)*2,          g_kl + src);
            CP16(d + (2*64*AP)*2,        g_vh + src);
            CP16(d + (3*64*AP)*2,        g_vl + src);
        }
    };

    const int kvmax = 2 * qt + 1;
    issue_kv(0, 0); CPCOMMIT();

    const int mr = qt * 128 + warp * 16;      // warp's first global row
    float m0 = -1e30f, m1 = -1e30f, l0 = 0.f, l1 = 0.f;
    float oacc[8][4];
#pragma unroll
    for (int d = 0; d < 8; d++)
#pragma unroll
        for (int r = 0; r < 4; r++) oacc[d][r] = 0.f;

    const uint32_t qhB = sbase + SQH * 2;
    const uint32_t qlB = sbase + SQL * 2;
    const int rowA_l = warp * 16 + (lane & 15);
    const int colA_l = (lane >> 4) * 8;
    const int rowB_l = (lane & 7) + ((lane >> 4) << 3);
    const int colB_l = ((lane >> 3) & 1) * 8;

    for (int kv = 0; kv <= kvmax; kv++) {
        CPWAIT0();
        __syncthreads();
        if (kv < kvmax) issue_kv((kv + 1) & 1, kv + 1);
        CPCOMMIT();

        const int nc = kv * 64;
        if (nc <= mr + 15) {   // tile not fully masked for this warp
            const uint32_t stg = sbase + (uint32_t)(SKV0 + (kv & 1) * KVSTAGE) * 2;
            const uint32_t khB = stg;
            const uint32_t klB = stg + (64*AP)*2;
            const uint32_t vhB = stg + (2*64*AP)*2;
            const uint32_t vlB = stg + (3*64*AP)*2;

            // ---- S = QK^T (bf16x3) ----
            float s[8][4];
#pragma unroll
            for (int jn = 0; jn < 8; jn++)
#pragma unroll
                for (int r = 0; r < 4; r++) s[jn][r] = 0.f;

#pragma unroll
            for (int pass = 0; pass < 3; pass++) {
                const uint32_t aB = (pass < 2) ? qhB : qlB;
                const uint32_t bB = (pass == 1) ? klB : khB;
#pragma unroll
                for (int k16 = 0; k16 < 4; k16++) {
                    uint32_t a[4];
                    LDMX4(a[0], a[1], a[2], a[3],
                          aB + (uint32_t)(rowA_l * AP + k16 * 16 + colA_l) * 2);
#pragma unroll
                    for (int nb = 0; nb < 4; nb++) {
                        uint32_t bb[4];
                        LDMX4(bb[0], bb[1], bb[2], bb[3],
                              bB + (uint32_t)((nb * 16 + rowB_l) * AP + k16 * 16 + colB_l) * 2);
                        MMA16816(s[nb*2],   a[0], a[1], a[2], a[3], bb[0], bb[1]);
                        MMA16816(s[nb*2+1], a[0], a[1], a[2], a[3], bb[2], bb[3]);
                    }
                }
            }

            // ---- causal mask ----
            if (nc + 63 > mr) {
#pragma unroll
                for (int jn = 0; jn < 8; jn++)
#pragma unroll
                    for (int e = 0; e < 2; e++) {
                        const int col = nc + jn * 8 + lr * 2 + e;
                        if (col > mr + lq)     s[jn][e]     = -1e30f;
                        if (col > mr + lq + 8) s[jn][e + 2] = -1e30f;
                    }
            }

            // ---- online softmax (base 2) ----
            float mx0 = -1e30f, mx1 = -1e30f;
#pragma unroll
            for (int jn = 0; jn < 8; jn++) {
                mx0 = fmaxf(mx0, fmaxf(s[jn][0], s[jn][1]));
                mx1 = fmaxf(mx1, fmaxf(s[jn][2], s[jn][3]));
            }
            mx0 = fmaxf(mx0, __shfl_xor_sync(0xffffffffu, mx0, 1));
            mx0 = fmaxf(mx0, __shfl_xor_sync(0xffffffffu, mx0, 2));
            mx1 = fmaxf(mx1, __shfl_xor_sync(0xffffffffu, mx1, 1));
            mx1 = fmaxf(mx1, __shfl_xor_sync(0xffffffffu, mx1, 2));
            const float mn0 = fmaxf(m0, mx0), mn1 = fmaxf(m1, mx1);
            const float c0 = ex2f(m0 - mn0), c1 = ex2f(m1 - mn1);
            m0 = mn0; m1 = mn1;
            float rs0 = 0.f, rs1 = 0.f;
#pragma unroll
            for (int jn = 0; jn < 8; jn++) {
                s[jn][0] = ex2f(s[jn][0] - mn0);
                s[jn][1] = ex2f(s[jn][1] - mn0);
                s[jn][2] = ex2f(s[jn][2] - mn1);
                s[jn][3] = ex2f(s[jn][3] - mn1);
                rs0 += s[jn][0] + s[jn][1];
                rs1 += s[jn][2] + s[jn][3];
            }
            rs0 += __shfl_xor_sync(0xffffffffu, rs0, 1);
            rs0 += __shfl_xor_sync(0xffffffffu, rs0, 2);
            rs1 += __shfl_xor_sync(0xffffffffu, rs1, 1);
            rs1 += __shfl_xor_sync(0xffffffffu, rs1, 2);
            l0 = l0 * c0 + rs0;
            l1 = l1 * c1 + rs1;
#pragma unroll
            for (int d = 0; d < 8; d++) {
                oacc[d][0] *= c0; oacc[d][1] *= c0;
                oacc[d][2] *= c1; oacc[d][3] *= c1;
            }

            // ---- pack P into A-fragments (hi/lo) ----
            uint32_t ph[4][4], pl[4][4];
#pragma unroll
            for (int kk = 0; kk < 4; kk++) {
                const int j0 = kk * 2, j1 = kk * 2 + 1;
                split2(s[j0][0], s[j0][1], ph[kk][0], pl[kk][0]);
                split2(s[j0][2], s[j0][3], ph[kk][1], pl[kk][1]);
                split2(s[j1][0], s[j1][1], ph[kk][2], pl[kk][2]);
                split2(s[j1][2], s[j1][3], ph[kk][3], pl[kk][3]);
            }

            // ---- O += P V (bf16x3) ----
#pragma unroll
            for (int kk = 0; kk < 4; kk++) {
#pragma unroll
                for (int db = 0; db < 4; db++) {
                    uint32_t v[4];
                    LDMX4T(v[0], v[1], v[2], v[3],
                           vhB + (uint32_t)((kk * 16 + (lane & 15)) * AP + db * 16 + colA_l) * 2);
                    MMA16816(oacc[db*2],   ph[kk][0], ph[kk][1], ph[kk][2], ph[kk][3], v[0], v[1]);
                    MMA16816(oacc[db*2+1], ph[kk][0], ph[kk][1], ph[kk][2], ph[kk][3], v[2], v[3]);
                    MMA16816(oacc[db*2],   pl[kk][0], pl[kk][1], pl[kk][2], pl[kk][3], v[0], v[1]);
                    MMA16816(oacc[db*2+1], pl[kk][0], pl[kk][1], pl[kk][2], pl[kk][3], v[2], v[3]);
                    LDMX4T(v[0], v[1], v[2], v[3],
                           vlB + (uint32_t)((kk * 16 + (lane & 15)) * AP + db * 16 + colA_l) * 2);
                    MMA16816(oacc[db*2],   ph[kk][0], ph[kk][1], ph[kk][2], ph[kk][3], v[0], v[1]);
                    MMA16816(oacc[db*2+1], ph[kk][0], ph[kk][1], ph[kk][2], ph[kk][3], v[2], v[3]);
                }
            }
        }
        __syncthreads();
    }

    // ---- epilogue: normalize, split, write y (bf16 hi/lo) into g_ah/g_al ----
    const float inv0 = rcpf(l0), inv1 = rcpf(l1);
    const int t0 = qt * 128 + warp * 16 + lq;
    const size_t base0 = ((size_t)b * T_ + t0) * C_ + h * 64;
    const size_t base1 = base0 + (size_t)8 * C_;
#pragma unroll
    for (int jn = 0; jn < 8; jn++) {
        const int col = jn * 8 + lr * 2;
        uint32_t hi, lo;
        split2(oacc[jn][0] * inv0, oacc[jn][1] * inv0, hi, lo);
        *(uint32_t*)(g_ah + base0 + col) = hi;
        *(uint32_t*)(g_al + base0 + col) = lo;
        split2(oacc[jn][2] * inv1, oacc[jn][3] * inv1, hi, lo);
        *(uint32_t*)(g_ah + base1 + col) = hi;
        *(uint32_t*)(g_al + base1 + col) = lo;
    }
}

// ---------------------------------------------------------------------------
extern "C" void kernel_launch(void* const* d_in, const int* in_sizes, int n_in,
                              void* d_out, int out_size)
{
    (void)in_sizes; (void)n_in; (void)out_size;
    const float* x     = (const float*)d_in[0];
    const float* Wqkv  = (const float*)d_in[1];
    const float* bqkv  = (const float*)d_in[2];
    const float* Wproj = (const float*)d_in[3];
    const float* bproj = (const float*)d_in[4];
    float* out = (float*)d_out;

    static int inited = 0;
    if (!inited) {
        cudaFuncSetAttribute(gemm_hmma<1>, cudaFuncAttributeMaxDynamicSharedMemorySize, GSMEM_BYTES);
        cudaFuncSetAttribute(gemm_hmma<2>, cudaFuncAttributeMaxDynamicSharedMemorySize, GSMEM_BYTES);
        cudaFuncSetAttribute(attn_hmma,    cudaFuncAttributeMaxDynamicSharedMemorySize, ATTN_SMEM_BYTES);
        inited = 1;
    }

    __nv_bfloat16 *ah, *al, *wqh, *wql, *wph, *wpl;
    cudaGetSymbolAddress((void**)&ah,  g_ah);
    cudaGetSymbolAddress((void**)&al,  g_al);
    cudaGetSymbolAddress((void**)&wqh, g_wqh);
    cudaGetSymbolAddress((void**)&wql, g_wql);
    cudaGetSymbolAddress((void**)&wph, g_wph);
    cudaGetSymbolAddress((void**)&wpl, g_wpl);

    // 1) split x and weights to bf16 hi/lo
    split_kernel<<<(M_*C_/4 + 255)/256, 256>>>(x, ah, al, M_*C_/4);
    split_kernel<<<(3*C_*C_/4 + 255)/256, 256>>>(Wqkv, wqh, wql, 3*C_*C_/4);
    split_kernel<<<(C_*C_/4 + 255)/256, 256>>>(Wproj, wph, wpl, C_*C_/4);

    // 2) QKV projection -> split bf16 q/k/v (q pre-scaled for base-2 softmax)
    gemm_hmma<1><<<dim3(3*C_/128, M_/128), 256, GSMEM_BYTES>>>(ah, al, wqh, wql, bqkv, nullptr);

    // 3) causal flash attention (HMMA) -> split bf16 y into g_ah/g_al
    attn_hmma<<<dim3(T_/128, NH_, B_), 256, ATTN_SMEM_BYTES>>>();

    // 4) output projection -> d_out
    gemm_hmma<2><<<dim3(C_/128, M_/128), 256, GSMEM_BYTES>>>(ah, al, wph, wpl, bproj, out);
}